// round 3
// baseline (speedup 1.0000x reference)
#include <cuda_runtime.h>

typedef unsigned long long u64;

// Problem constants
#define BB 4
#define CC 32
#define DW 64
#define HH 256
#define WW 256
#define HW 65536

// Scratch (device globals: allocation-free rule)
__device__ float g_t[BB * DW * HW];    // conv1(LN(inp)) output, 64 MB
__device__ float g_xsg[BB * CC * HW];  // gate output, 32 MB
__device__ float g_part[BB * CC * 64]; // per-(b,ch,tile) partial sums
__device__ float g_s[BB * CC];         // SCA scale per (b,ch)

// ---- packed fp32x2 helpers (sm_100+) ----
__device__ __forceinline__ u64 pack2(float lo, float hi) {
    u64 r;
    asm("mov.b64 %0, {%1,%2};" : "=l"(r) : "f"(lo), "f"(hi));
    return r;
}
__device__ __forceinline__ float2 unpack2(u64 v) {
    float lo, hi;
    asm("mov.b64 {%0,%1}, %2;" : "=f"(lo), "=f"(hi) : "l"(v));
    return make_float2(lo, hi);
}
__device__ __forceinline__ u64 ffma2(u64 a, u64 b, u64 c) {
    u64 d;
    asm("fma.rn.f32x2 %0, %1, %2, %3;" : "=l"(d) : "l"(a), "l"(b), "l"(c));
    return d;
}
__device__ __forceinline__ u64 mul2(u64 a, u64 b) {
    u64 d;
    asm("mul.rn.f32x2 %0, %1, %2;" : "=l"(d) : "l"(a), "l"(b));
    return d;
}

// =====================================================================
// K1: LayerNorm(channel) + conv1 (32 -> 64) as a register-blocked GEMM
// over a 128-pixel tile. 128 threads: tm=tid>>4 owns 8 outputs,
// tx=tid&15 owns 8 pixels (4 f32x2 pairs).
// =====================================================================
__global__ __launch_bounds__(128) void k1(const float* __restrict__ inp,
                                          const float* __restrict__ w1,
                                          const float* __restrict__ b1g,
                                          const float* __restrict__ n1w,
                                          const float* __restrict__ n1b) {
    __shared__ float is_[32 * 128];   // input tile
    __shared__ float zs[32 * 128];    // LN output tile
    __shared__ float w1s[32 * 64];    // w1s[k][o]

    int tid = threadIdx.x;
    int bid = blockIdx.x;
    int b = bid >> 9;
    int pix0 = (bid & 511) << 7;

    // stage input tile + transposed weights
    for (int i = tid; i < 1024; i += 128) {
        int c = i >> 5, q = i & 31;
        *(float4*)&is_[c * 128 + q * 4] =
            *(const float4*)&inp[(b * CC + c) * HW + pix0 + q * 4];
    }
    for (int i = tid; i < 2048; i += 128) {
        int o = i >> 5, k = i & 31;
        w1s[k * 64 + o] = w1[i];
    }
    __syncthreads();

    // per-pixel LayerNorm (thread tid -> pixel tid; conflict-free columns)
    {
        float col[32];
        float s = 0.f, s2 = 0.f;
#pragma unroll
        for (int c = 0; c < 32; c++) {
            col[c] = is_[c * 128 + tid];
            s += col[c];
            s2 += col[c] * col[c];
        }
        float mu = s * (1.f / 32.f);
        float var = s2 * (1.f / 32.f) - mu * mu;
        float rstd = rsqrtf(var + 1e-6f);
#pragma unroll
        for (int c = 0; c < 32; c++)
            zs[c * 128 + tid] = (col[c] - mu) * rstd * n1w[c] + n1b[c];
    }
    __syncthreads();

    // conv1 GEMM: M=64, K=32, N=128 pixels
    int tx = tid & 15, tm = tid >> 4;
    int px = pix0 + (tx << 3);
    u64 acc[8][4];
#pragma unroll
    for (int j = 0; j < 8; j++) {
        float bv = b1g[8 * tm + j];
#pragma unroll
        for (int q = 0; q < 4; q++) acc[j][q] = pack2(bv, bv);
    }
#pragma unroll
    for (int k = 0; k < 32; k++) {
        float4 wA = *(float4*)&w1s[k * 64 + 8 * tm];
        float4 wB = *(float4*)&w1s[k * 64 + 8 * tm + 4];
        ulonglong2 xa = *(ulonglong2*)&zs[k * 128 + (tx << 3)];
        ulonglong2 xb = *(ulonglong2*)&zs[k * 128 + (tx << 3) + 4];
        u64 xv[4] = {xa.x, xa.y, xb.x, xb.y};
        u64 wd[8] = {pack2(wA.x, wA.x), pack2(wA.y, wA.y), pack2(wA.z, wA.z),
                     pack2(wA.w, wA.w), pack2(wB.x, wB.x), pack2(wB.y, wB.y),
                     pack2(wB.z, wB.z), pack2(wB.w, wB.w)};
#pragma unroll
        for (int j = 0; j < 8; j++)
#pragma unroll
            for (int q = 0; q < 4; q++) acc[j][q] = ffma2(wd[j], xv[q], acc[j][q]);
    }
#pragma unroll
    for (int j = 0; j < 8; j++) {
        int o = 8 * tm + j;
        float2 f0 = unpack2(acc[j][0]), f1 = unpack2(acc[j][1]);
        float2 f2 = unpack2(acc[j][2]), f3 = unpack2(acc[j][3]);
        float* op = g_t + (b * DW + o) * HW + px;
        *(float4*)op = make_float4(f0.x, f0.y, f1.x, f1.y);
        *(float4*)(op + 4) = make_float4(f2.x, f2.y, f3.x, f3.y);
    }
}

// =====================================================================
// K2: DDF (bilinear-upsampled per-pixel 3x3 filter) + SimpleGate
//     + per-tile partial channel sums for SCA. (unchanged)
// =====================================================================
__global__ __launch_bounds__(128) void k2(const float* __restrict__ w2g) {
    int tile = blockIdx.x;  // 0..63
    int chp = blockIdx.y;   // 0..31
    int b = blockIdx.z;
    int tyi = tile >> 3, txi = tile & 7;
    int h0 = tyi * 32, w0 = txi * 32;
    const int TSTR = 35;

    __shared__ float tin[2][34 * TSTR];
    __shared__ float Wc[2][9][36];
    __shared__ float red[4];

    int tid = threadIdx.x;

#pragma unroll
    for (int cc = 0; cc < 2; cc++) {
        const float* src = g_t + (b * DW + chp + cc * 32) * HW;
        for (int idx = tid; idx < 34 * 34; idx += 128) {
            int r = idx / 34, c = idx - r * 34;
            int gh = h0 - 1 + r, gw = w0 - 1 + c;
            float v = 0.f;
            if ((unsigned)gh < 256u && (unsigned)gw < 256u) v = src[gh * 256 + gw];
            tin[cc][r * TSTR + c] = v;
        }
    }
    {
        int ybase = 4 * tyi - 1, xbase = 4 * txi - 1;
        for (int idx = tid; idx < 648; idx += 128) {
            int cc = idx / 324;
            int rem = idx - cc * 324;
            int t = rem / 36;
            int rc = rem - t * 36;
            int rr = rc / 6, cj = rc - rr * 6;
            int ys = min(max(ybase + rr, 0), 31);
            int xs = min(max(xbase + cj, 0), 31);
            Wc[cc][t][rc] =
                w2g[(((b * 64 + chp + cc * 32) * 9 + t) * 32 + ys) * 32 + xs];
        }
    }
    __syncthreads();

    int row = tid >> 2;
    int seg = (tid & 3) * 8;
    int h = h0 + row;

    float srcy = (h - 3.5f) * 0.125f;
    float y0f = floorf(srcy);
    float fy = srcy - y0f;
    int y0 = (int)y0f;
    int ybase = 4 * tyi - 1;
    int y0l = max(y0, 0) - ybase;
    int y1l = min(y0 + 1, 31) - ybase;

    int m = 4 * txi + (seg >> 3);
    int xbase = 4 * txi - 1;
    int a0 = max(m - 1, 0) - xbase;
    int a1 = m - xbase;
    int b1i = min(m + 1, 31) - xbase;

    float acc[2][8];
#pragma unroll
    for (int cc = 0; cc < 2; cc++) {
        float ra[10], rb[10], rc[10];
#pragma unroll
        for (int k = 0; k < 10; k++) {
            ra[k] = tin[cc][row * TSTR + seg + k];
            rb[k] = tin[cc][(row + 1) * TSTR + seg + k];
            rc[k] = tin[cc][(row + 2) * TSTR + seg + k];
        }
#pragma unroll
        for (int i = 0; i < 8; i++) acc[cc][i] = 0.f;

#define TAP(RR, T, DX)                                              \
    {                                                               \
        const float* Wp = Wc[cc][T];                                \
        float v0a = Wp[y0l * 6 + a0], v0b = Wp[y1l * 6 + a0];       \
        float v1a = Wp[y0l * 6 + a1], v1b = Wp[y1l * 6 + a1];       \
        float v2a = Wp[y0l * 6 + b1i], v2b = Wp[y1l * 6 + b1i];     \
        float v0 = v0a + fy * (v0b - v0a);                          \
        float v1 = v1a + fy * (v1b - v1a);                          \
        float v2 = v2a + fy * (v2b - v2a);                          \
        float dA = v1 - v0, dB = v2 - v1;                           \
        acc[cc][0] += (v0 + 0.5625f * dA) * RR[0 + DX];             \
        acc[cc][1] += (v0 + 0.6875f * dA) * RR[1 + DX];             \
        acc[cc][2] += (v0 + 0.8125f * dA) * RR[2 + DX];             \
        acc[cc][3] += (v0 + 0.9375f * dA) * RR[3 + DX];             \
        acc[cc][4] += (v1 + 0.0625f * dB) * RR[4 + DX];             \
        acc[cc][5] += (v1 + 0.1875f * dB) * RR[5 + DX];             \
        acc[cc][6] += (v1 + 0.3125f * dB) * RR[6 + DX];             \
        acc[cc][7] += (v1 + 0.4375f * dB) * RR[7 + DX];             \
    }
        TAP(ra, 0, 0) TAP(ra, 1, 1) TAP(ra, 2, 2)
        TAP(rb, 3, 0) TAP(rb, 4, 1) TAP(rb, 5, 2)
        TAP(rc, 6, 0) TAP(rc, 7, 1) TAP(rc, 8, 2)
#undef TAP
    }

    float g[8];
    float tsum = 0.f;
#pragma unroll
    for (int i = 0; i < 8; i++) {
        g[i] = acc[0][i] * acc[1][i];
        tsum += g[i];
    }
    float* op = g_xsg + (b * CC + chp) * HW + h * 256 + w0 + seg;
    *(float4*)(op) = make_float4(g[0], g[1], g[2], g[3]);
    *(float4*)(op + 4) = make_float4(g[4], g[5], g[6], g[7]);

#pragma unroll
    for (int off = 16; off; off >>= 1)
        tsum += __shfl_xor_sync(0xffffffffu, tsum, off);
    if ((tid & 31) == 0) red[tid >> 5] = tsum;
    __syncthreads();
    if (tid == 0)
        g_part[(b * CC + chp) * 64 + tile] = red[0] + red[1] + red[2] + red[3];
}

// =====================================================================
// K3: deterministic reduction of partials + SCA 1x1 conv -> g_s
// =====================================================================
__global__ void k3(const float* __restrict__ sw, const float* __restrict__ sbias) {
    __shared__ float mean_sm[128];
    int tid = threadIdx.x;
    int b = tid >> 5, c = tid & 31;
    float sum = 0.f;
    for (int t = 0; t < 64; t++) sum += g_part[(b * CC + c) * 64 + t];
    mean_sm[tid] = sum * (1.f / 65536.f);
    __syncthreads();
    float acc = sbias[c];
#pragma unroll
    for (int k = 0; k < 32; k++) acc += sw[c * 32 + k] * mean_sm[b * 32 + k];
    g_s[tid] = acc;
}

// =====================================================================
// K4: x*s -> conv3 -> y=inp+beta*x -> LN2 -> conv4 -> gate -> conv5
//     -> out = y + gamma*z.  Register-blocked GEMMs over a 128-pixel tile.
// 128 threads: tm=tid>>4 owns 4 outputs (or 4 (o,o+32) pairs in conv4),
// tx=tid&15 owns 8 pixels as 4 f32x2 pairs.
// =====================================================================
__global__ __launch_bounds__(128) void k4(const float* __restrict__ inp,
                                          const float* __restrict__ w3,
                                          const float* __restrict__ b3g,
                                          const float* __restrict__ w4,
                                          const float* __restrict__ b4g,
                                          const float* __restrict__ w5,
                                          const float* __restrict__ b5g,
                                          const float* __restrict__ n2wg,
                                          const float* __restrict__ n2bg,
                                          const float* __restrict__ betag,
                                          const float* __restrict__ gammag,
                                          float* __restrict__ out) {
    __shared__ float xs[32 * 128];   // x (scaled) tile, later LN2 output
    __shared__ float ys[32 * 128];   // y tile, later gate-output tile
    __shared__ float w35s[32 * 32];  // w3s[k][o], restaged with w5 after conv3
    __shared__ float w4s[32 * 64];   // w4s[k][2p]=w4[p][k], [2p+1]=w4[p+32][k]

    int tid = threadIdx.x;
    int bid = blockIdx.x;
    int b = bid >> 9;
    int pix0 = (bid & 511) << 7;
    int tx = tid & 15, tm = tid >> 4;
    int px = pix0 + (tx << 3);

    // stage x = g_xsg * s, and weights (transposed)
    for (int i = tid; i < 1024; i += 128) {
        int c = i >> 5, q = i & 31;
        float s = g_s[b * 32 + c];
        float4 v = *(const float4*)&g_xsg[(b * CC + c) * HW + pix0 + q * 4];
        *(float4*)&xs[c * 128 + q * 4] =
            make_float4(v.x * s, v.y * s, v.z * s, v.w * s);
    }
    for (int i = tid; i < 1024; i += 128) {
        int o = i >> 5, k = i & 31;
        w35s[k * 32 + o] = w3[i];
    }
    for (int i = tid; i < 2048; i += 128) {
        int o = i >> 5, k = i & 31;
        int j = (o < 32) ? 2 * o : 2 * (o - 32) + 1;
        w4s[k * 64 + j] = w4[i];
    }
    __syncthreads();

    // ---- conv3 GEMM (M=32) ----
    u64 acc[4][4];
#pragma unroll
    for (int j = 0; j < 4; j++) {
        float bv = b3g[4 * tm + j];
#pragma unroll
        for (int q = 0; q < 4; q++) acc[j][q] = pack2(bv, bv);
    }
#pragma unroll
    for (int k = 0; k < 32; k++) {
        float4 wv = *(float4*)&w35s[k * 32 + 4 * tm];
        ulonglong2 xa = *(ulonglong2*)&xs[k * 128 + (tx << 3)];
        ulonglong2 xb = *(ulonglong2*)&xs[k * 128 + (tx << 3) + 4];
        u64 xv[4] = {xa.x, xa.y, xb.x, xb.y};
        u64 wd[4] = {pack2(wv.x, wv.x), pack2(wv.y, wv.y), pack2(wv.z, wv.z),
                     pack2(wv.w, wv.w)};
#pragma unroll
        for (int j = 0; j < 4; j++)
#pragma unroll
            for (int q = 0; q < 4; q++) acc[j][q] = ffma2(wd[j], xv[q], acc[j][q]);
    }

    // conv3 epilogue: y = inp + beta * conv3; keep y in regs + smem
    float yv[4][8];
#pragma unroll
    for (int j = 0; j < 4; j++) {
        int ch = 4 * tm + j;
        const float* ipc = inp + (b * CC + ch) * HW + px;
        float4 iA = *(const float4*)ipc;
        float4 iB = *(const float4*)(ipc + 4);
        float bt = betag[ch];
        float2 f0 = unpack2(acc[j][0]), f1 = unpack2(acc[j][1]);
        float2 f2 = unpack2(acc[j][2]), f3 = unpack2(acc[j][3]);
        yv[j][0] = iA.x + bt * f0.x;
        yv[j][1] = iA.y + bt * f0.y;
        yv[j][2] = iA.z + bt * f1.x;
        yv[j][3] = iA.w + bt * f1.y;
        yv[j][4] = iB.x + bt * f2.x;
        yv[j][5] = iB.y + bt * f2.y;
        yv[j][6] = iB.z + bt * f3.x;
        yv[j][7] = iB.w + bt * f3.y;
        *(float4*)&ys[ch * 128 + (tx << 3)] =
            make_float4(yv[j][0], yv[j][1], yv[j][2], yv[j][3]);
        *(float4*)&ys[ch * 128 + (tx << 3) + 4] =
            make_float4(yv[j][4], yv[j][5], yv[j][6], yv[j][7]);
    }
    __syncthreads();

    // ---- LN2 (thread -> pixel) + restage w5 into w35s ----
    for (int i = tid; i < 1024; i += 128) {
        int o = i >> 5, k = i & 31;
        w35s[k * 32 + o] = w5[i];
    }
    {
        float col[32];
        float s = 0.f, s2 = 0.f;
#pragma unroll
        for (int c = 0; c < 32; c++) {
            col[c] = ys[c * 128 + tid];
            s += col[c];
            s2 += col[c] * col[c];
        }
        float mu = s * (1.f / 32.f);
        float var = s2 * (1.f / 32.f) - mu * mu;
        float rstd = rsqrtf(var + 1e-6f);
#pragma unroll
        for (int c = 0; c < 32; c++)
            xs[c * 128 + tid] = (col[c] - mu) * rstd * n2wg[c] + n2bg[c];
    }
    __syncthreads();

    // ---- conv4 GEMM (M=64 as 32 (o,o+32) pairs) + gate ----
    {
        u64 alo[4][4], ahi[4][4];
#pragma unroll
        for (int j = 0; j < 4; j++) {
            float bl = b4g[4 * tm + j];
            float bh = b4g[4 * tm + j + 32];
#pragma unroll
            for (int q = 0; q < 4; q++) {
                alo[j][q] = pack2(bl, bl);
                ahi[j][q] = pack2(bh, bh);
            }
        }
#pragma unroll
        for (int k = 0; k < 32; k++) {
            float4 wA = *(float4*)&w4s[k * 64 + 8 * tm];
            float4 wB = *(float4*)&w4s[k * 64 + 8 * tm + 4];
            ulonglong2 xa = *(ulonglong2*)&xs[k * 128 + (tx << 3)];
            ulonglong2 xb = *(ulonglong2*)&xs[k * 128 + (tx << 3) + 4];
            u64 xv[4] = {xa.x, xa.y, xb.x, xb.y};
            u64 wl[4] = {pack2(wA.x, wA.x), pack2(wA.z, wA.z),
                         pack2(wB.x, wB.x), pack2(wB.z, wB.z)};
            u64 wh[4] = {pack2(wA.y, wA.y), pack2(wA.w, wA.w),
                         pack2(wB.y, wB.y), pack2(wB.w, wB.w)};
#pragma unroll
            for (int j = 0; j < 4; j++)
#pragma unroll
                for (int q = 0; q < 4; q++) {
                    alo[j][q] = ffma2(wl[j], xv[q], alo[j][q]);
                    ahi[j][q] = ffma2(wh[j], xv[q], ahi[j][q]);
                }
        }
        // gate -> ys
#pragma unroll
        for (int j = 0; j < 4; j++) {
            int ch = 4 * tm + j;
            ulonglong2 r0, r1;
            r0.x = mul2(alo[j][0], ahi[j][0]);
            r0.y = mul2(alo[j][1], ahi[j][1]);
            r1.x = mul2(alo[j][2], ahi[j][2]);
            r1.y = mul2(alo[j][3], ahi[j][3]);
            *(ulonglong2*)&ys[ch * 128 + (tx << 3)] = r0;
            *(ulonglong2*)&ys[ch * 128 + (tx << 3) + 4] = r1;
        }
    }
    __syncthreads();

    // ---- conv5 GEMM (M=32) + final residual ----
#pragma unroll
    for (int j = 0; j < 4; j++) {
        float bv = b5g[4 * tm + j];
#pragma unroll
        for (int q = 0; q < 4; q++) acc[j][q] = pack2(bv, bv);
    }
#pragma unroll
    for (int k = 0; k < 32; k++) {
        float4 wv = *(float4*)&w35s[k * 32 + 4 * tm];
        ulonglong2 xa = *(ulonglong2*)&ys[k * 128 + (tx << 3)];
        ulonglong2 xb = *(ulonglong2*)&ys[k * 128 + (tx << 3) + 4];
        u64 xv[4] = {xa.x, xa.y, xb.x, xb.y};
        u64 wd[4] = {pack2(wv.x, wv.x), pack2(wv.y, wv.y), pack2(wv.z, wv.z),
                     pack2(wv.w, wv.w)};
#pragma unroll
        for (int j = 0; j < 4; j++)
#pragma unroll
            for (int q = 0; q < 4; q++) acc[j][q] = ffma2(wd[j], xv[q], acc[j][q]);
    }
#pragma unroll
    for (int j = 0; j < 4; j++) {
        int ch = 4 * tm + j;
        float gm = gammag[ch];
        float2 f0 = unpack2(acc[j][0]), f1 = unpack2(acc[j][1]);
        float2 f2 = unpack2(acc[j][2]), f3 = unpack2(acc[j][3]);
        float* op = out + (b * CC + ch) * HW + px;
        *(float4*)op = make_float4(yv[j][0] + gm * f0.x, yv[j][1] + gm * f0.y,
                                   yv[j][2] + gm * f1.x, yv[j][3] + gm * f1.y);
        *(float4*)(op + 4) =
            make_float4(yv[j][4] + gm * f2.x, yv[j][5] + gm * f2.y,
                        yv[j][6] + gm * f3.x, yv[j][7] + gm * f3.y);
    }
}

extern "C" void kernel_launch(void* const* d_in, const int* in_sizes, int n_in,
                              void* d_out, int out_size) {
    const float* inp     = (const float*)d_in[0];
    const float* w2      = (const float*)d_in[1];
    const float* conv1_w = (const float*)d_in[2];
    const float* conv1_b = (const float*)d_in[3];
    const float* conv3_w = (const float*)d_in[4];
    const float* conv3_b = (const float*)d_in[5];
    const float* sca_w   = (const float*)d_in[6];
    const float* sca_b   = (const float*)d_in[7];
    const float* conv4_w = (const float*)d_in[8];
    const float* conv4_b = (const float*)d_in[9];
    const float* conv5_w = (const float*)d_in[10];
    const float* conv5_b = (const float*)d_in[11];
    const float* norm1_w = (const float*)d_in[12];
    const float* norm1_b = (const float*)d_in[13];
    const float* norm2_w = (const float*)d_in[14];
    const float* norm2_b = (const float*)d_in[15];
    const float* beta    = (const float*)d_in[16];
    const float* gamma   = (const float*)d_in[17];
    float* out = (float*)d_out;

    k1<<<2048, 128>>>(inp, conv1_w, conv1_b, norm1_w, norm1_b);
    k2<<<dim3(64, 32, 4), 128>>>(w2);
    k3<<<1, 128>>>(sca_w, sca_b);
    k4<<<2048, 128>>>(inp, conv3_w, conv3_b, conv4_w, conv4_b, conv5_w, conv5_b,
                      norm2_w, norm2_b, beta, gamma, out);
}

// round 4
// speedup vs baseline: 1.1335x; 1.1335x over previous
#include <cuda_runtime.h>

typedef unsigned long long u64;

// Problem constants
#define BB 4
#define CC 32
#define DW 64
#define HH 256
#define WW 256
#define HW 65536

// Scratch (device globals: allocation-free rule)
__device__ float g_t[BB * DW * HW];    // conv1(LN(inp)) output, 64 MB
__device__ float g_xsg[BB * CC * HW];  // gate output, 32 MB
__device__ float g_part[BB * CC * 64]; // per-(b,ch,tile) partial sums
__device__ float g_s[BB * CC];         // SCA scale per (b,ch)

// ---- packed fp32x2 helpers (sm_100+) ----
__device__ __forceinline__ u64 pack2(float lo, float hi) {
    u64 r;
    asm("mov.b64 %0, {%1,%2};" : "=l"(r) : "f"(lo), "f"(hi));
    return r;
}
__device__ __forceinline__ float2 unpack2(u64 v) {
    float lo, hi;
    asm("mov.b64 {%0,%1}, %2;" : "=f"(lo), "=f"(hi) : "l"(v));
    return make_float2(lo, hi);
}
__device__ __forceinline__ u64 ffma2(u64 a, u64 b, u64 c) {
    u64 d;
    asm("fma.rn.f32x2 %0, %1, %2, %3;" : "=l"(d) : "l"(a), "l"(b), "l"(c));
    return d;
}
__device__ __forceinline__ u64 mul2(u64 a, u64 b) {
    u64 d;
    asm("mul.rn.f32x2 %0, %1, %2;" : "=l"(d) : "l"(a), "l"(b));
    return d;
}

// =====================================================================
// K1: LayerNorm(channel) + conv1 (32 -> 64), register-blocked GEMM over
// a 128-pixel tile. tx=tid&15 owns pixels {tx*4..+3} and {64+tx*4..+3}
// (conflict-free LDS.128), tm=tid>>4 owns 8 outputs.
// =====================================================================
__global__ __launch_bounds__(128) void k1(const float* __restrict__ inp,
                                          const float* __restrict__ w1,
                                          const float* __restrict__ b1g,
                                          const float* __restrict__ n1w,
                                          const float* __restrict__ n1b) {
    __shared__ float is_[32 * 128];   // input tile
    __shared__ float zs[32 * 128];    // LN output tile
    __shared__ float w1s[32 * 64];    // w1s[k][o]

    int tid = threadIdx.x;
    int bid = blockIdx.x;
    int b = bid >> 9;
    int pix0 = (bid & 511) << 7;

    for (int i = tid; i < 1024; i += 128) {
        int c = i >> 5, q = i & 31;
        *(float4*)&is_[c * 128 + q * 4] =
            *(const float4*)&inp[(b * CC + c) * HW + pix0 + q * 4];
    }
    for (int i = tid; i < 2048; i += 128) {
        int o = i >> 5, k = i & 31;
        w1s[k * 64 + o] = w1[i];
    }
    __syncthreads();

    // per-pixel LayerNorm (thread -> pixel; contiguous columns)
    {
        float col[32];
        float s = 0.f, s2 = 0.f;
#pragma unroll
        for (int c = 0; c < 32; c++) {
            col[c] = is_[c * 128 + tid];
            s += col[c];
            s2 += col[c] * col[c];
        }
        float mu = s * (1.f / 32.f);
        float var = s2 * (1.f / 32.f) - mu * mu;
        float rstd = rsqrtf(var + 1e-6f);
#pragma unroll
        for (int c = 0; c < 32; c++)
            zs[c * 128 + tid] = (col[c] - mu) * rstd * n1w[c] + n1b[c];
    }
    __syncthreads();

    int tx = tid & 15, tm = tid >> 4;
    u64 acc[8][4];
#pragma unroll
    for (int j = 0; j < 8; j++) {
        float bv = b1g[8 * tm + j];
#pragma unroll
        for (int q = 0; q < 4; q++) acc[j][q] = pack2(bv, bv);
    }
#pragma unroll
    for (int k = 0; k < 32; k++) {
        float4 wA = *(float4*)&w1s[k * 64 + 8 * tm];
        float4 wB = *(float4*)&w1s[k * 64 + 8 * tm + 4];
        ulonglong2 xa = *(ulonglong2*)&zs[k * 128 + tx * 4];       // px lo
        ulonglong2 xb = *(ulonglong2*)&zs[k * 128 + 64 + tx * 4];  // px hi
        u64 xv[4] = {xa.x, xa.y, xb.x, xb.y};
        u64 wd[8] = {pack2(wA.x, wA.x), pack2(wA.y, wA.y), pack2(wA.z, wA.z),
                     pack2(wA.w, wA.w), pack2(wB.x, wB.x), pack2(wB.y, wB.y),
                     pack2(wB.z, wB.z), pack2(wB.w, wB.w)};
#pragma unroll
        for (int j = 0; j < 8; j++)
#pragma unroll
            for (int q = 0; q < 4; q++) acc[j][q] = ffma2(wd[j], xv[q], acc[j][q]);
    }
#pragma unroll
    for (int j = 0; j < 8; j++) {
        int o = 8 * tm + j;
        float2 f0 = unpack2(acc[j][0]), f1 = unpack2(acc[j][1]);
        float2 f2 = unpack2(acc[j][2]), f3 = unpack2(acc[j][3]);
        float* op = g_t + (b * DW + o) * HW + pix0 + tx * 4;
        *(float4*)op = make_float4(f0.x, f0.y, f1.x, f1.y);
        *(float4*)(op + 64) = make_float4(f2.x, f2.y, f3.x, f3.y);
    }
}

// =====================================================================
// K2: DDF (bilinear-upsampled per-pixel 3x3 filter) + SimpleGate
//     + per-tile partial channel sums for SCA. (unchanged)
// =====================================================================
__global__ __launch_bounds__(128) void k2(const float* __restrict__ w2g) {
    int tile = blockIdx.x;
    int chp = blockIdx.y;
    int b = blockIdx.z;
    int tyi = tile >> 3, txi = tile & 7;
    int h0 = tyi * 32, w0 = txi * 32;
    const int TSTR = 35;

    __shared__ float tin[2][34 * TSTR];
    __shared__ float Wc[2][9][36];
    __shared__ float red[4];

    int tid = threadIdx.x;

#pragma unroll
    for (int cc = 0; cc < 2; cc++) {
        const float* src = g_t + (b * DW + chp + cc * 32) * HW;
        for (int idx = tid; idx < 34 * 34; idx += 128) {
            int r = idx / 34, c = idx - r * 34;
            int gh = h0 - 1 + r, gw = w0 - 1 + c;
            float v = 0.f;
            if ((unsigned)gh < 256u && (unsigned)gw < 256u) v = src[gh * 256 + gw];
            tin[cc][r * TSTR + c] = v;
        }
    }
    {
        int ybase = 4 * tyi - 1, xbase = 4 * txi - 1;
        for (int idx = tid; idx < 648; idx += 128) {
            int cc = idx / 324;
            int rem = idx - cc * 324;
            int t = rem / 36;
            int rc = rem - t * 36;
            int rr = rc / 6, cj = rc - rr * 6;
            int ys = min(max(ybase + rr, 0), 31);
            int xs = min(max(xbase + cj, 0), 31);
            Wc[cc][t][rc] =
                w2g[(((b * 64 + chp + cc * 32) * 9 + t) * 32 + ys) * 32 + xs];
        }
    }
    __syncthreads();

    int row = tid >> 2;
    int seg = (tid & 3) * 8;
    int h = h0 + row;

    float srcy = (h - 3.5f) * 0.125f;
    float y0f = floorf(srcy);
    float fy = srcy - y0f;
    int y0 = (int)y0f;
    int ybase = 4 * tyi - 1;
    int y0l = max(y0, 0) - ybase;
    int y1l = min(y0 + 1, 31) - ybase;

    int m = 4 * txi + (seg >> 3);
    int xbase = 4 * txi - 1;
    int a0 = max(m - 1, 0) - xbase;
    int a1 = m - xbase;
    int b1i = min(m + 1, 31) - xbase;

    float acc[2][8];
#pragma unroll
    for (int cc = 0; cc < 2; cc++) {
        float ra[10], rb[10], rc[10];
#pragma unroll
        for (int k = 0; k < 10; k++) {
            ra[k] = tin[cc][row * TSTR + seg + k];
            rb[k] = tin[cc][(row + 1) * TSTR + seg + k];
            rc[k] = tin[cc][(row + 2) * TSTR + seg + k];
        }
#pragma unroll
        for (int i = 0; i < 8; i++) acc[cc][i] = 0.f;

#define TAP(RR, T, DX)                                              \
    {                                                               \
        const float* Wp = Wc[cc][T];                                \
        float v0a = Wp[y0l * 6 + a0], v0b = Wp[y1l * 6 + a0];       \
        float v1a = Wp[y0l * 6 + a1], v1b = Wp[y1l * 6 + a1];       \
        float v2a = Wp[y0l * 6 + b1i], v2b = Wp[y1l * 6 + b1i];     \
        float v0 = v0a + fy * (v0b - v0a);                          \
        float v1 = v1a + fy * (v1b - v1a);                          \
        float v2 = v2a + fy * (v2b - v2a);                          \
        float dA = v1 - v0, dB = v2 - v1;                           \
        acc[cc][0] += (v0 + 0.5625f * dA) * RR[0 + DX];             \
        acc[cc][1] += (v0 + 0.6875f * dA) * RR[1 + DX];             \
        acc[cc][2] += (v0 + 0.8125f * dA) * RR[2 + DX];             \
        acc[cc][3] += (v0 + 0.9375f * dA) * RR[3 + DX];             \
        acc[cc][4] += (v1 + 0.0625f * dB) * RR[4 + DX];             \
        acc[cc][5] += (v1 + 0.1875f * dB) * RR[5 + DX];             \
        acc[cc][6] += (v1 + 0.3125f * dB) * RR[6 + DX];             \
        acc[cc][7] += (v1 + 0.4375f * dB) * RR[7 + DX];             \
    }
        TAP(ra, 0, 0) TAP(ra, 1, 1) TAP(ra, 2, 2)
        TAP(rb, 3, 0) TAP(rb, 4, 1) TAP(rb, 5, 2)
        TAP(rc, 6, 0) TAP(rc, 7, 1) TAP(rc, 8, 2)
#undef TAP
    }

    float g[8];
    float tsum = 0.f;
#pragma unroll
    for (int i = 0; i < 8; i++) {
        g[i] = acc[0][i] * acc[1][i];
        tsum += g[i];
    }
    float* op = g_xsg + (b * CC + chp) * HW + h * 256 + w0 + seg;
    *(float4*)(op) = make_float4(g[0], g[1], g[2], g[3]);
    *(float4*)(op + 4) = make_float4(g[4], g[5], g[6], g[7]);

#pragma unroll
    for (int off = 16; off; off >>= 1)
        tsum += __shfl_xor_sync(0xffffffffu, tsum, off);
    if ((tid & 31) == 0) red[tid >> 5] = tsum;
    __syncthreads();
    if (tid == 0)
        g_part[(b * CC + chp) * 64 + tile] = red[0] + red[1] + red[2] + red[3];
}

// =====================================================================
// K3: deterministic reduction of partials + SCA 1x1 conv -> g_s
// =====================================================================
__global__ void k3(const float* __restrict__ sw, const float* __restrict__ sbias) {
    __shared__ float mean_sm[128];
    int tid = threadIdx.x;
    int b = tid >> 5, c = tid & 31;
    float sum = 0.f;
    for (int t = 0; t < 64; t++) sum += g_part[(b * CC + c) * 64 + t];
    mean_sm[tid] = sum * (1.f / 65536.f);
    __syncthreads();
    float acc = sbias[c];
#pragma unroll
    for (int k = 0; k < 32; k++) acc += sw[c * 32 + k] * mean_sm[b * 32 + k];
    g_s[tid] = acc;
}

// =====================================================================
// K4: x*s -> conv3 -> y=inp+beta*x -> LN2 -> conv4 -> gate -> conv5
//     -> out = y + gamma*z. Register-blocked GEMMs, 128-pixel tile.
// Conflict-free addressing: tx owns pixel chunks {tx*4} and {64+tx*4}.
// =====================================================================
__global__ __launch_bounds__(128) void k4(const float* __restrict__ inp,
                                          const float* __restrict__ w3,
                                          const float* __restrict__ b3g,
                                          const float* __restrict__ w4,
                                          const float* __restrict__ b4g,
                                          const float* __restrict__ w5,
                                          const float* __restrict__ b5g,
                                          const float* __restrict__ n2wg,
                                          const float* __restrict__ n2bg,
                                          const float* __restrict__ betag,
                                          const float* __restrict__ gammag,
                                          float* __restrict__ out) {
    __shared__ float xs[32 * 128];   // x tile, later LN2 output
    __shared__ float ys[32 * 128];   // y tile, later gate-output tile
    __shared__ float w35s[32 * 32];  // w3 (transposed), restaged with w5
    __shared__ float w4s[32 * 64];   // w4s[k][2p]=w4[p][k], [2p+1]=w4[p+32][k]

    int tid = threadIdx.x;
    int bid = blockIdx.x;
    int b = bid >> 9;
    int pix0 = (bid & 511) << 7;
    int tx = tid & 15, tm = tid >> 4;

    for (int i = tid; i < 1024; i += 128) {
        int c = i >> 5, q = i & 31;
        float s = g_s[b * 32 + c];
        float4 v = *(const float4*)&g_xsg[(b * CC + c) * HW + pix0 + q * 4];
        *(float4*)&xs[c * 128 + q * 4] =
            make_float4(v.x * s, v.y * s, v.z * s, v.w * s);
    }
    for (int i = tid; i < 1024; i += 128) {
        int o = i >> 5, k = i & 31;
        w35s[k * 32 + o] = w3[i];
    }
    for (int i = tid; i < 2048; i += 128) {
        int o = i >> 5, k = i & 31;
        int j = (o < 32) ? 2 * o : 2 * (o - 32) + 1;
        w4s[k * 64 + j] = w4[i];
    }
    __syncthreads();

    // ---- conv3 GEMM (M=32) ----
    u64 acc[4][4];
#pragma unroll
    for (int j = 0; j < 4; j++) {
        float bv = b3g[4 * tm + j];
#pragma unroll
        for (int q = 0; q < 4; q++) acc[j][q] = pack2(bv, bv);
    }
#pragma unroll
    for (int k = 0; k < 32; k++) {
        float4 wv = *(float4*)&w35s[k * 32 + 4 * tm];
        ulonglong2 xa = *(ulonglong2*)&xs[k * 128 + tx * 4];
        ulonglong2 xb = *(ulonglong2*)&xs[k * 128 + 64 + tx * 4];
        u64 xv[4] = {xa.x, xa.y, xb.x, xb.y};
        u64 wd[4] = {pack2(wv.x, wv.x), pack2(wv.y, wv.y), pack2(wv.z, wv.z),
                     pack2(wv.w, wv.w)};
#pragma unroll
        for (int j = 0; j < 4; j++)
#pragma unroll
            for (int q = 0; q < 4; q++) acc[j][q] = ffma2(wd[j], xv[q], acc[j][q]);
    }

    // conv3 epilogue: y = inp + beta * conv3
    float yv[4][8];
#pragma unroll
    for (int j = 0; j < 4; j++) {
        int ch = 4 * tm + j;
        const float* ipc = inp + (b * CC + ch) * HW + pix0 + tx * 4;
        float4 iA = *(const float4*)ipc;
        float4 iB = *(const float4*)(ipc + 64);
        float bt = betag[ch];
        float2 f0 = unpack2(acc[j][0]), f1 = unpack2(acc[j][1]);
        float2 f2 = unpack2(acc[j][2]), f3 = unpack2(acc[j][3]);
        yv[j][0] = iA.x + bt * f0.x;
        yv[j][1] = iA.y + bt * f0.y;
        yv[j][2] = iA.z + bt * f1.x;
        yv[j][3] = iA.w + bt * f1.y;
        yv[j][4] = iB.x + bt * f2.x;
        yv[j][5] = iB.y + bt * f2.y;
        yv[j][6] = iB.z + bt * f3.x;
        yv[j][7] = iB.w + bt * f3.y;
        *(float4*)&ys[ch * 128 + tx * 4] =
            make_float4(yv[j][0], yv[j][1], yv[j][2], yv[j][3]);
        *(float4*)&ys[ch * 128 + 64 + tx * 4] =
            make_float4(yv[j][4], yv[j][5], yv[j][6], yv[j][7]);
    }
    __syncthreads();

    // ---- LN2 + restage w5 ----
    for (int i = tid; i < 1024; i += 128) {
        int o = i >> 5, k = i & 31;
        w35s[k * 32 + o] = w5[i];
    }
    {
        float col[32];
        float s = 0.f, s2 = 0.f;
#pragma unroll
        for (int c = 0; c < 32; c++) {
            col[c] = ys[c * 128 + tid];
            s += col[c];
            s2 += col[c] * col[c];
        }
        float mu = s * (1.f / 32.f);
        float var = s2 * (1.f / 32.f) - mu * mu;
        float rstd = rsqrtf(var + 1e-6f);
#pragma unroll
        for (int c = 0; c < 32; c++)
            xs[c * 128 + tid] = (col[c] - mu) * rstd * n2wg[c] + n2bg[c];
    }
    __syncthreads();

    // ---- conv4 GEMM (M=64 as 32 (o,o+32) pairs) + gate ----
    {
        u64 alo[4][4], ahi[4][4];
#pragma unroll
        for (int j = 0; j < 4; j++) {
            float bl = b4g[4 * tm + j];
            float bh = b4g[4 * tm + j + 32];
#pragma unroll
            for (int q = 0; q < 4; q++) {
                alo[j][q] = pack2(bl, bl);
                ahi[j][q] = pack2(bh, bh);
            }
        }
#pragma unroll
        for (int k = 0; k < 32; k++) {
            float4 wA = *(float4*)&w4s[k * 64 + 8 * tm];
            float4 wB = *(float4*)&w4s[k * 64 + 8 * tm + 4];
            ulonglong2 xa = *(ulonglong2*)&xs[k * 128 + tx * 4];
            ulonglong2 xb = *(ulonglong2*)&xs[k * 128 + 64 + tx * 4];
            u64 xv[4] = {xa.x, xa.y, xb.x, xb.y};
            u64 wl[4] = {pack2(wA.x, wA.x), pack2(wA.z, wA.z),
                         pack2(wB.x, wB.x), pack2(wB.z, wB.z)};
            u64 wh[4] = {pack2(wA.y, wA.y), pack2(wA.w, wA.w),
                         pack2(wB.y, wB.y), pack2(wB.w, wB.w)};
#pragma unroll
            for (int j = 0; j < 4; j++)
#pragma unroll
                for (int q = 0; q < 4; q++) {
                    alo[j][q] = ffma2(wl[j], xv[q], alo[j][q]);
                    ahi[j][q] = ffma2(wh[j], xv[q], ahi[j][q]);
                }
        }
#pragma unroll
        for (int j = 0; j < 4; j++) {
            int ch = 4 * tm + j;
            ulonglong2 r0, r1;
            r0.x = mul2(alo[j][0], ahi[j][0]);
            r0.y = mul2(alo[j][1], ahi[j][1]);
            r1.x = mul2(alo[j][2], ahi[j][2]);
            r1.y = mul2(alo[j][3], ahi[j][3]);
            *(ulonglong2*)&ys[ch * 128 + tx * 4] = r0;
            *(ulonglong2*)&ys[ch * 128 + 64 + tx * 4] = r1;
        }
    }
    __syncthreads();

    // ---- conv5 GEMM (M=32) + final residual ----
#pragma unroll
    for (int j = 0; j < 4; j++) {
        float bv = b5g[4 * tm + j];
#pragma unroll
        for (int q = 0; q < 4; q++) acc[j][q] = pack2(bv, bv);
    }
#pragma unroll
    for (int k = 0; k < 32; k++) {
        float4 wv = *(float4*)&w35s[k * 32 + 4 * tm];
        ulonglong2 xa = *(ulonglong2*)&ys[k * 128 + tx * 4];
        ulonglong2 xb = *(ulonglong2*)&ys[k * 128 + 64 + tx * 4];
        u64 xv[4] = {xa.x, xa.y, xb.x, xb.y};
        u64 wd[4] = {pack2(wv.x, wv.x), pack2(wv.y, wv.y), pack2(wv.z, wv.z),
                     pack2(wv.w, wv.w)};
#pragma unroll
        for (int j = 0; j < 4; j++)
#pragma unroll
            for (int q = 0; q < 4; q++) acc[j][q] = ffma2(wd[j], xv[q], acc[j][q]);
    }
#pragma unroll
    for (int j = 0; j < 4; j++) {
        int ch = 4 * tm + j;
        float gm = gammag[ch];
        float2 f0 = unpack2(acc[j][0]), f1 = unpack2(acc[j][1]);
        float2 f2 = unpack2(acc[j][2]), f3 = unpack2(acc[j][3]);
        float* op = out + (b * CC + ch) * HW + pix0 + tx * 4;
        *(float4*)op = make_float4(yv[j][0] + gm * f0.x, yv[j][1] + gm * f0.y,
                                   yv[j][2] + gm * f1.x, yv[j][3] + gm * f1.y);
        *(float4*)(op + 64) =
            make_float4(yv[j][4] + gm * f2.x, yv[j][5] + gm * f2.y,
                        yv[j][6] + gm * f3.x, yv[j][7] + gm * f3.y);
    }
}

extern "C" void kernel_launch(void* const* d_in, const int* in_sizes, int n_in,
                              void* d_out, int out_size) {
    const float* inp     = (const float*)d_in[0];
    const float* w2      = (const float*)d_in[1];
    const float* conv1_w = (const float*)d_in[2];
    const float* conv1_b = (const float*)d_in[3];
    const float* conv3_w = (const float*)d_in[4];
    const float* conv3_b = (const float*)d_in[5];
    const float* sca_w   = (const float*)d_in[6];
    const float* sca_b   = (const float*)d_in[7];
    const float* conv4_w = (const float*)d_in[8];
    const float* conv4_b = (const float*)d_in[9];
    const float* conv5_w = (const float*)d_in[10];
    const float* conv5_b = (const float*)d_in[11];
    const float* norm1_w = (const float*)d_in[12];
    const float* norm1_b = (const float*)d_in[13];
    const float* norm2_w = (const float*)d_in[14];
    const float* norm2_b = (const float*)d_in[15];
    const float* beta    = (const float*)d_in[16];
    const float* gamma   = (const float*)d_in[17];
    float* out = (float*)d_out;

    k1<<<2048, 128>>>(inp, conv1_w, conv1_b, norm1_w, norm1_b);
    k2<<<dim3(64, 32, 4), 128>>>(w2);
    k3<<<1, 128>>>(sca_w, sca_b);
    k4<<<2048, 128>>>(inp, conv3_w, conv3_b, conv4_w, conv4_b, conv5_w, conv5_b,
                      norm2_w, norm2_b, beta, gamma, out);
}